// round 9
// baseline (speedup 1.0000x reference)
#include <cuda_runtime.h>
#include <cuda_bf16.h>
#include <mma.h>
#include <cstdint>

using namespace nvcuda;

// Problem constants
#define Bn 512
#define Dn 768
#define Ln 128
#define Rn 128
#define BD (Bn * Dn)
#define BD4 (BD / 4)
#define ROW4 (Dn / 4)        // 192
#define KCg 64               // fp32 K-cols per chunk (bf16 K=64)
#define NCHUNK (Dn / KCg)    // 12
#define PLDb 72              // bf16 plane leading dim (elements), mult of 8
#define ATTLD 132            // att leading dim (floats)
#define EPS 2e-4f            // covers worst-case bf16-split error with margin

// Output offsets (floats), reference tuple order
#define LD_OFF 0ull
#define RD_OFF 50331648ull
#define LM_OFF 100663296ull
#define RM_OFF 100728832ull
#define LS_OFF 100794368ull
#define RS_OFF 100859904ull

// bf16 plane element offsets
#define AH_OFF 0
#define AM_OFF (128 * PLDb)
#define BH_OFF (2 * 128 * PLDb)
#define BM_OFF (3 * 128 * PLDb)
#define PLANE_ELEMS (4 * 128 * PLDb)
#define DSMEM_BYTES (PLANE_ELEMS * 2)      // 73728 B (>= att 128*132*4 = 67584)

// Scratch
__device__ float  g_invL[Ln * Dn];
__device__ float  g_invR[Rn * Dn];
__device__ double g_inv64L[Ln * Dn];
__device__ double g_inv64R[Rn * Dn];
__device__ int    g_lidx[Bn * Ln];
__device__ int    g_ridx[Bn * Rn];

// fp32 pair -> (hi, mid) bf16x2: lower half = a (even col), upper = b (odd col)
__device__ __forceinline__ void split_pair(float a, float b, uint32_t& h, uint32_t& m) {
    asm("cvt.rn.bf16x2.f32 %0, %1, %2;" : "=r"(h) : "f"(b), "f"(a));
    float ha = __uint_as_float(h << 16);
    float hb = __uint_as_float(h & 0xffff0000u);
    float ra = a - ha, rb = b - hb;
    asm("cvt.rn.bf16x2.f32 %0, %1, %2;" : "=r"(m) : "f"(rb), "f"(ra));
}

// ---------------------------------------------------------------------------
// Kernel 1: inv norms over batch axis. float4 loads, 4-wide b-unroll for MLP,
// fp64 accumulation (must stay exact: feeds the dot64 tie-break ground truth).
// One thread per (side, l, 4 d's). 128-thread blocks for SM spread.
// ---------------------------------------------------------------------------
__global__ __launch_bounds__(128) void norms_kernel(const float* __restrict__ left,
                                                    const float* __restrict__ right) {
    int gid = blockIdx.x * blockDim.x + threadIdx.x;   // [0, 2*Ln*ROW4)
    const int PER = Ln * ROW4;                         // 24576 float4 per side
    const float* src;
    float* dst32;
    double* dst64;
    int idx4;
    if (gid < PER) { src = left;  dst32 = g_invL; dst64 = g_inv64L; idx4 = gid; }
    else           { src = right; dst32 = g_invR; dst64 = g_inv64R; idx4 = gid - PER; }
    int l  = idx4 / ROW4;
    int d4 = idx4 - l * ROW4;
    const float4* p = (const float4*)(src + (size_t)l * BD) + d4;

    double a0 = 0.0, a1 = 0.0, a2 = 0.0, a3 = 0.0;
#pragma unroll 4
    for (int b = 0; b < Bn; b += 4) {
        float4 v0 = p[(size_t)(b + 0) * ROW4];
        float4 v1 = p[(size_t)(b + 1) * ROW4];
        float4 v2 = p[(size_t)(b + 2) * ROW4];
        float4 v3 = p[(size_t)(b + 3) * ROW4];
        a0 += (double)v0.x * v0.x + (double)v1.x * v1.x
            + (double)v2.x * v2.x + (double)v3.x * v3.x;
        a1 += (double)v0.y * v0.y + (double)v1.y * v1.y
            + (double)v2.y * v2.y + (double)v3.y * v3.y;
        a2 += (double)v0.z * v0.z + (double)v1.z * v1.z
            + (double)v2.z * v2.z + (double)v3.z * v3.z;
        a3 += (double)v0.w * v0.w + (double)v1.w * v1.w
            + (double)v2.w * v2.w + (double)v3.w * v3.w;
    }
    int e = l * Dn + d4 * 4;
    double i0 = 1.0 / sqrt(a0), i1 = 1.0 / sqrt(a1);
    double i2 = 1.0 / sqrt(a2), i3 = 1.0 / sqrt(a3);
    dst64[e + 0] = i0; dst64[e + 1] = i1; dst64[e + 2] = i2; dst64[e + 3] = i3;
    dst32[e + 0] = (float)i0; dst32[e + 1] = (float)i1;
    dst32[e + 2] = (float)i2; dst32[e + 3] = (float)i3;
}

// ---------------------------------------------------------------------------
// Warp-collective fp64 normalized dot (ground truth for near-ties)
// ---------------------------------------------------------------------------
__device__ __forceinline__ double dot64(const float* __restrict__ left,
                                        const float* __restrict__ right,
                                        int l, int r, int b) {
    const int lane = threadIdx.x & 31;
    const float*  lp = left  + (size_t)l * BD + (size_t)b * Dn;
    const float*  rp = right + (size_t)r * BD + (size_t)b * Dn;
    const double* il = g_inv64L + l * Dn;
    const double* ir = g_inv64R + r * Dn;
    double acc = 0.0;
    for (int d = lane; d < Dn; d += 32)
        acc += (double)lp[d] * (double)rp[d] * il[d] * ir[d];
#pragma unroll
    for (int off = 16; off; off >>= 1)
        acc += __shfl_xor_sync(0xffffffffu, acc, off);
    return acc;
}

// ---------------------------------------------------------------------------
// Kernel 2: one CTA per batch. bf16 2-plane 3-product wmma GEMM + max/argmax.
// Planes pre-zeroed once; per chunk only rows < len are converted.
// ---------------------------------------------------------------------------
__global__ __launch_bounds__(256, 2) void main_kernel(const float* __restrict__ left,
                                                      const int*   __restrict__ llen,
                                                      const float* __restrict__ right,
                                                      const int*   __restrict__ rlen,
                                                      float*       __restrict__ out) {
    const int b    = blockIdx.x;
    const int tid  = threadIdx.x;
    const int wid  = tid >> 5;
    const int lane = tid & 31;
    const int warp_m = wid >> 1;   // 0..3: C rows [32*warp_m, +32)
    const int warp_n = wid & 1;    // 0..1: C cols [64*warp_n, +64)

    __shared__ float lm[Ln];
    __shared__ float rm[Rn];

    extern __shared__ float smem[];
    __nv_bfloat16* pl = (__nv_bfloat16*)smem;   // bf16 planes
    float* att = smem;                           // aliases planes after GEMM

    const int ll = llen[b];
    const int rl = rlen[b];

    // -------- masks + plane pre-zero (covers masked rows for every chunk) ----
    if (tid < 128) {
        float lmv = (tid < ll) ? 1.0f : 0.0f;
        float rmv = (tid < rl) ? 1.0f : 0.0f;
        lm[tid] = lmv;
        rm[tid] = rmv;
        out[LM_OFF + (size_t)b * Ln + tid] = lmv;
        out[RM_OFF + (size_t)b * Rn + tid] = rmv;
    }
    {
        uint4* p4 = (uint4*)pl;
        const int n4 = PLANE_ELEMS / 8;          // 4608 uint4
        for (int i = tid; i < n4; i += 256)
            p4[i] = make_uint4(0u, 0u, 0u, 0u);
    }

    // -------- GEMM: bf16 hi/mid, products hh + hm + mh --------
    wmma::fragment<wmma::accumulator, 16, 16, 16, float> cf[2][4];
#pragma unroll
    for (int i = 0; i < 2; i++)
#pragma unroll
        for (int j = 0; j < 4; j++) wmma::fill_fragment(cf[i][j], 0.0f);

    const float* lbase = left  + (size_t)b * Dn;
    const float* rbase = right + (size_t)b * Dn;

    const bool act0 = (32 * warp_m      < ll);
    const bool act1 = (32 * warp_m + 16 < ll);
    const int  nA = ll * 16;    // active A work items (row * 16 quads)
    const int  nB = rl * 16;

    __syncthreads();   // planes zeroed before first conversion

    for (int c = 0; c < NCHUNK; c++) {
        const int c0 = c * KCg;

        // convert only active rows
        for (int i = tid; i < nA; i += 256) {
            int row = i >> 4;
            int dq  = (i & 15) << 2;
            float4 v  = *(const float4*)(lbase + (size_t)row * BD + c0 + dq);
            float4 nv = *(const float4*)(g_invL + row * Dn + c0 + dq);
            uint32_t h01, m01, h23, m23;
            split_pair(v.x * nv.x, v.y * nv.y, h01, m01);
            split_pair(v.z * nv.z, v.w * nv.w, h23, m23);
            int e = row * PLDb + dq;
            *(uint2*)(pl + AH_OFF + e) = make_uint2(h01, h23);
            *(uint2*)(pl + AM_OFF + e) = make_uint2(m01, m23);
        }
        for (int i = tid; i < nB; i += 256) {
            int row = i >> 4;
            int dq  = (i & 15) << 2;
            float4 v  = *(const float4*)(rbase + (size_t)row * BD + c0 + dq);
            float4 nv = *(const float4*)(g_invR + row * Dn + c0 + dq);
            uint32_t h01, m01, h23, m23;
            split_pair(v.x * nv.x, v.y * nv.y, h01, m01);
            split_pair(v.z * nv.z, v.w * nv.w, h23, m23);
            int e = row * PLDb + dq;
            *(uint2*)(pl + BH_OFF + e) = make_uint2(h01, h23);
            *(uint2*)(pl + BM_OFF + e) = make_uint2(m01, m23);
        }
        __syncthreads();

        if (act0) {
#pragma unroll
            for (int ks = 0; ks < KCg / 16; ks++) {
                const int k0 = ks * 16;
                wmma::fragment<wmma::matrix_a, 16, 16, 16, __nv_bfloat16,
                               wmma::row_major> ah[2], am[2];
                {
                    const int r0 = 32 * warp_m;
                    wmma::load_matrix_sync(ah[0], pl + AH_OFF + r0 * PLDb + k0, PLDb);
                    wmma::load_matrix_sync(am[0], pl + AM_OFF + r0 * PLDb + k0, PLDb);
                    if (act1) {
                        wmma::load_matrix_sync(ah[1], pl + AH_OFF + (r0 + 16) * PLDb + k0, PLDb);
                        wmma::load_matrix_sync(am[1], pl + AM_OFF + (r0 + 16) * PLDb + k0, PLDb);
                    }
                }
#pragma unroll
                for (int n = 0; n < 4; n++) {
                    const int n0 = 64 * warp_n + 16 * n;
                    if (n0 >= rl) continue;                 // B tile fully masked
                    wmma::fragment<wmma::matrix_b, 16, 16, 16, __nv_bfloat16,
                                   wmma::col_major> bh, bm;
                    wmma::load_matrix_sync(bh, pl + BH_OFF + n0 * PLDb + k0, PLDb);
                    wmma::load_matrix_sync(bm, pl + BM_OFF + n0 * PLDb + k0, PLDb);
                    wmma::mma_sync(cf[0][n], ah[0], bh, cf[0][n]);
                    wmma::mma_sync(cf[0][n], am[0], bh, cf[0][n]);
                    wmma::mma_sync(cf[0][n], ah[0], bm, cf[0][n]);
                    if (act1) {
                        wmma::mma_sync(cf[1][n], ah[1], bh, cf[1][n]);
                        wmma::mma_sync(cf[1][n], am[1], bh, cf[1][n]);
                        wmma::mma_sync(cf[1][n], ah[1], bm, cf[1][n]);
                    }
                }
            }
        }
        __syncthreads();
    }

    // -------- epilogue: fragments -> att, then mask in place --------
#pragma unroll
    for (int i = 0; i < 2; i++)
#pragma unroll
        for (int n = 0; n < 4; n++) {
            const int r0 = 32 * warp_m + 16 * i;
            const int n0 = 64 * warp_n + 16 * n;
            wmma::store_matrix_sync(att + r0 * ATTLD + n0, cf[i][n], ATTLD,
                                    wmma::mem_row_major);
        }
    __syncthreads();

#pragma unroll
    for (int j = 0; j < 16; j++) {
        int i4  = tid + 256 * j;          // 4096 float4 = 128 x 128
        int row = i4 >> 5;
        int c4  = (i4 & 31) << 2;
        float4* p = (float4*)(att + row * ATTLD + c4);
        float4 v = *p;
        float lmv = lm[row];
        v.x *= lmv * rm[c4 + 0];
        v.y *= lmv * rm[c4 + 1];
        v.z *= lmv * rm[c4 + 2];
        v.w *= lmv * rm[c4 + 3];
        *p = v;
    }
    __syncthreads();

    // -------- reductions with fp64 near-tie refinement --------
    for (int r8 = 0; r8 < 16; r8++) {
        int row = wid * 16 + r8;
        float best = att[row * ATTLD + lane];
        int   bi   = lane;
#pragma unroll
        for (int m = 1; m < 4; m++) {
            float v = att[row * ATTLD + lane + 32 * m];
            if (v > best) { best = v; bi = lane + 32 * m; }
        }
#pragma unroll
        for (int off = 16; off; off >>= 1) {
            float ov = __shfl_xor_sync(0xffffffffu, best, off);
            int   oi = __shfl_xor_sync(0xffffffffu, bi,   off);
            if (ov > best || (ov == best && oi < bi)) { best = ov; bi = oi; }
        }
        float thr = best - EPS;
        int cnt = 0;
#pragma unroll
        for (int m = 0; m < 4; m++) {
            float v = att[row * ATTLD + m * 32 + lane];
            cnt += __popc(__ballot_sync(0xffffffffu, v >= thr));
        }
        int fi = bi;
        if (cnt >= 2) {
            bool zmode = (best == 0.0f);
            double bbest;
            int    bbi;
            if (zmode) { bbest = 0.0; bbi = bi; }
            else       { bbest = -1e300; bbi = -1; }
#pragma unroll
            for (int m = 0; m < 4; m++) {
                float v = att[row * ATTLD + m * 32 + lane];
                bool near = (v >= thr) && (!zmode || v != 0.0f);
                unsigned bal = __ballot_sync(0xffffffffu, near);
                while (bal) {
                    int ln = __ffs(bal) - 1;
                    bal &= bal - 1;
                    int cand = m * 32 + ln;
                    bool masked = (lm[row] == 0.0f) || (rm[cand] == 0.0f);
                    double val = masked ? 0.0 : dot64(left, right, row, cand, b);
                    if (val > bbest || (val == bbest && cand < bbi)) { bbest = val; bbi = cand; }
                }
            }
            fi = bbi;
        }
        if (lane == 0) {
            out[LS_OFF + (size_t)row * Bn + b] = att[row * ATTLD + fi];
            g_lidx[b * Ln + row] = fi;
        }
    }

    for (int c8 = 0; c8 < 16; c8++) {
        int col = wid * 16 + c8;
        float best = att[lane * ATTLD + col];
        int   bi   = lane;
#pragma unroll
        for (int m = 1; m < 4; m++) {
            float v = att[(lane + 32 * m) * ATTLD + col];
            if (v > best) { best = v; bi = lane + 32 * m; }
        }
#pragma unroll
        for (int off = 16; off; off >>= 1) {
            float ov = __shfl_xor_sync(0xffffffffu, best, off);
            int   oi = __shfl_xor_sync(0xffffffffu, bi,   off);
            if (ov > best || (ov == best && oi < bi)) { best = ov; bi = oi; }
        }
        float thr = best - EPS;
        int cnt = 0;
#pragma unroll
        for (int m = 0; m < 4; m++) {
            float v = att[(m * 32 + lane) * ATTLD + col];
            cnt += __popc(__ballot_sync(0xffffffffu, v >= thr));
        }
        int fi = bi;
        if (cnt >= 2) {
            bool zmode = (best == 0.0f);
            double bbest;
            int    bbi;
            if (zmode) { bbest = 0.0; bbi = bi; }
            else       { bbest = -1e300; bbi = -1; }
#pragma unroll
            for (int m = 0; m < 4; m++) {
                float v = att[(m * 32 + lane) * ATTLD + col];
                bool near = (v >= thr) && (!zmode || v != 0.0f);
                unsigned bal = __ballot_sync(0xffffffffu, near);
                while (bal) {
                    int ln = __ffs(bal) - 1;
                    bal &= bal - 1;
                    int cand = m * 32 + ln;
                    bool masked = (lm[cand] == 0.0f) || (rm[col] == 0.0f);
                    double val = masked ? 0.0 : dot64(left, right, cand, col, b);
                    if (val > bbest || (val == bbest && cand < bbi)) { bbest = val; bbi = cand; }
                }
            }
            fi = bbi;
        }
        if (lane == 0) {
            out[RS_OFF + (size_t)col * Bn + b] = att[fi * ATTLD + col];
            g_ridx[b * Rn + col] = fi;
        }
    }
}

// ---------------------------------------------------------------------------
// Kernel 3: difference gathers. One thread handles the same i4 for BOTH sides:
// shared index math, doubled independent loads in flight, same coalescing.
// ---------------------------------------------------------------------------
__global__ __launch_bounds__(256) void diff_kernel(const float* __restrict__ left,
                                                   const int*   __restrict__ llen,
                                                   const float* __restrict__ right,
                                                   const int*   __restrict__ rlen,
                                                   float*       __restrict__ out) {
    int i4 = blockIdx.x * blockDim.x + threadIdx.x;   // [0, PER_SIDE)

    int l   = i4 / (Bn * ROW4);
    int rem = i4 - l * (Bn * ROW4);
    int b   = rem / ROW4;
    int dq  = rem - b * ROW4;

    const float4* l4 = (const float4*)left;
    const float4* r4 = (const float4*)right;

    const int llv = llen[b];
    const int rlv = rlen[b];

    float4 resL = make_float4(0.f, 0.f, 0.f, 0.f);
    float4 resR = make_float4(0.f, 0.f, 0.f, 0.f);

    if (l < llv) {
        int idx = g_lidx[b * Ln + l];
        float4 a = l4[i4];
        float4 c = r4[(size_t)idx * BD4 + (size_t)b * ROW4 + dq];
        resL = make_float4(a.x - c.x, a.y - c.y, a.z - c.z, a.w - c.w);
    }
    if (l < rlv) {
        int idx = g_ridx[b * Rn + l];
        float4 a = r4[i4];
        float4 c = l4[(size_t)idx * BD4 + (size_t)b * ROW4 + dq];
        resR = make_float4(a.x - c.x, a.y - c.y, a.z - c.z, a.w - c.w);
    }
    ((float4*)(out + LD_OFF))[i4] = resL;
    ((float4*)(out + RD_OFF))[i4] = resR;
}

// ---------------------------------------------------------------------------
extern "C" void kernel_launch(void* const* d_in, const int* in_sizes, int n_in,
                              void* d_out, int out_size) {
    (void)in_sizes; (void)n_in; (void)out_size;
    const float* left  = (const float*)d_in[0];
    const int*   llen  = (const int*)d_in[1];
    const float* right = (const float*)d_in[2];
    const int*   rlen  = (const int*)d_in[3];
    float* out = (float*)d_out;

    cudaFuncSetAttribute(main_kernel, cudaFuncAttributeMaxDynamicSharedMemorySize,
                         DSMEM_BYTES);

    norms_kernel<<<(2 * Ln * ROW4) / 128, 128>>>(left, right);
    main_kernel<<<Bn, 256, DSMEM_BYTES>>>(left, llen, right, rlen, out);

    const int PER_SIDE = Ln * Bn * ROW4;
    diff_kernel<<<PER_SIDE / 256, 256>>>(left, llen, right, rlen, out);
}

// round 10
// speedup vs baseline: 1.0487x; 1.0487x over previous
#include <cuda_runtime.h>
#include <cuda_bf16.h>
#include <mma.h>
#include <cstdint>

using namespace nvcuda;

// Problem constants
#define Bn 512
#define Dn 768
#define Ln 128
#define Rn 128
#define BD (Bn * Dn)
#define BD4 (BD / 4)
#define ROW4 (Dn / 4)        // 192
#define KCg 64               // fp32 K-cols per chunk (bf16 K=64)
#define NCHUNK (Dn / KCg)    // 12
#define PLDb 72              // bf16 plane leading dim (elements), mult of 8
#define ATTLD 132            // att leading dim (floats)
#define EPS 2e-4f            // covers worst-case bf16-split error with margin

// Output offsets (floats), reference tuple order
#define LD_OFF 0ull
#define RD_OFF 50331648ull
#define LM_OFF 100663296ull
#define RM_OFF 100728832ull
#define LS_OFF 100794368ull
#define RS_OFF 100859904ull

// bf16 plane element offsets
#define AH_OFF 0
#define AM_OFF (128 * PLDb)
#define BH_OFF (2 * 128 * PLDb)
#define BM_OFF (3 * 128 * PLDb)
#define PLANE_ELEMS (4 * 128 * PLDb)
#define DSMEM_BYTES (PLANE_ELEMS * 2)      // 73728 B (>= att 128*132*4 = 67584)

// Scratch
__device__ float  g_invL[Ln * Dn];
__device__ float  g_invR[Rn * Dn];
__device__ double g_inv64L[Ln * Dn];
__device__ double g_inv64R[Rn * Dn];
__device__ int    g_lidx[Bn * Ln];
__device__ int    g_ridx[Bn * Rn];

// fp32 pair -> (hi, mid) bf16x2: lower half = a (even col), upper = b (odd col)
__device__ __forceinline__ void split_pair(float a, float b, uint32_t& h, uint32_t& m) {
    asm("cvt.rn.bf16x2.f32 %0, %1, %2;" : "=r"(h) : "f"(b), "f"(a));
    float ha = __uint_as_float(h << 16);
    float hb = __uint_as_float(h & 0xffff0000u);
    float ra = a - ha, rb = b - hb;
    asm("cvt.rn.bf16x2.f32 %0, %1, %2;" : "=r"(m) : "f"(rb), "f"(ra));
}

// ---------------------------------------------------------------------------
// Kernel 1: inv_n[l,d] = 1/sqrt(sum_b x[l,b,d]^2), fp64 accumulation.
// (R8 version — measured 69 us @ 74% DRAM; do not touch.)
// ---------------------------------------------------------------------------
__global__ __launch_bounds__(256) void norms_kernel(const float* __restrict__ left,
                                                    const float* __restrict__ right) {
    int gid = blockIdx.x * blockDim.x + threadIdx.x;
    const int LD = Ln * Dn;
    const float* src;
    float* dst32;
    double* dst64;
    int idx;
    if (gid < LD) { src = left;  dst32 = g_invL; dst64 = g_inv64L; idx = gid; }
    else          { src = right; dst32 = g_invR; dst64 = g_inv64R; idx = gid - LD; }
    int l = idx / Dn;
    int d = idx - l * Dn;
    const float* p = src + (size_t)l * BD + d;
    double acc = 0.0;
#pragma unroll 8
    for (int b = 0; b < Bn; b++) {
        double v = (double)p[(size_t)b * Dn];
        acc += v * v;
    }
    double inv = 1.0 / sqrt(acc);
    dst64[idx] = inv;
    dst32[idx] = (float)inv;
}

// ---------------------------------------------------------------------------
// Warp-collective fp64 normalized dot (ground truth for near-ties)
// ---------------------------------------------------------------------------
__device__ __forceinline__ double dot64(const float* __restrict__ left,
                                        const float* __restrict__ right,
                                        int l, int r, int b) {
    const int lane = threadIdx.x & 31;
    const float*  lp = left  + (size_t)l * BD + (size_t)b * Dn;
    const float*  rp = right + (size_t)r * BD + (size_t)b * Dn;
    const double* il = g_inv64L + l * Dn;
    const double* ir = g_inv64R + r * Dn;
    double acc = 0.0;
    for (int d = lane; d < Dn; d += 32)
        acc += (double)lp[d] * (double)rp[d] * il[d] * ir[d];
#pragma unroll
    for (int off = 16; off; off >>= 1)
        acc += __shfl_xor_sync(0xffffffffu, acc, off);
    return acc;
}

// ---------------------------------------------------------------------------
// Kernel 2: one CTA per batch. bf16 2-plane 3-product wmma GEMM + max/argmax.
// Planes pre-zeroed once; conversion loop static-unrolled with per-row
// predicate skipping the whole body for masked rows.
// ---------------------------------------------------------------------------
__global__ __launch_bounds__(256, 2) void main_kernel(const float* __restrict__ left,
                                                      const int*   __restrict__ llen,
                                                      const float* __restrict__ right,
                                                      const int*   __restrict__ rlen,
                                                      float*       __restrict__ out) {
    const int b    = blockIdx.x;
    const int tid  = threadIdx.x;
    const int wid  = tid >> 5;
    const int lane = tid & 31;
    const int warp_m = wid >> 1;   // 0..3: C rows [32*warp_m, +32)
    const int warp_n = wid & 1;    // 0..1: C cols [64*warp_n, +64)

    __shared__ float lm[Ln];
    __shared__ float rm[Rn];

    extern __shared__ float smem[];
    __nv_bfloat16* pl = (__nv_bfloat16*)smem;   // bf16 planes
    float* att = smem;                           // aliases planes after GEMM

    const int ll = llen[b];
    const int rl = rlen[b];

    // -------- masks + plane pre-zero (covers masked rows for every chunk) ----
    if (tid < 128) {
        float lmv = (tid < ll) ? 1.0f : 0.0f;
        float rmv = (tid < rl) ? 1.0f : 0.0f;
        lm[tid] = lmv;
        rm[tid] = rmv;
        out[LM_OFF + (size_t)b * Ln + tid] = lmv;
        out[RM_OFF + (size_t)b * Rn + tid] = rmv;
    }
    {
        uint4* p4 = (uint4*)pl;
        const int n4 = PLANE_ELEMS / 8;          // 4608 uint4
#pragma unroll
        for (int j = 0; j < 18; j++)
            p4[tid + 256 * j] = make_uint4(0u, 0u, 0u, 0u);
    }

    // -------- GEMM: bf16 hi/mid, products hh + hm + mh --------
    wmma::fragment<wmma::accumulator, 16, 16, 16, float> cf[2][4];
#pragma unroll
    for (int i = 0; i < 2; i++)
#pragma unroll
        for (int j = 0; j < 4; j++) wmma::fill_fragment(cf[i][j], 0.0f);

    const float* lbase = left  + (size_t)b * Dn;
    const float* rbase = right + (size_t)b * Dn;

    const bool act0 = (32 * warp_m      < ll);
    const bool act1 = (32 * warp_m + 16 < ll);

    // conversion geometry: item i covers (row = i>>4, quad = i&15); row spans
    // 16 contiguous threads so the per-row predicate diverges coarsely.
    const int crow = tid >> 4;
    const int cdq  = (tid & 15) << 2;

    __syncthreads();   // planes zeroed before first conversion

    for (int c = 0; c < NCHUNK; c++) {
        const int c0 = c * KCg;

        // convert active rows only (static unroll, predicated body)
#pragma unroll
        for (int j = 0; j < 8; j++) {
            int row = crow + 16 * j;       // 0..127
            int e   = row * PLDb + cdq;
            if (row < ll) {
                float4 v  = *(const float4*)(lbase + (size_t)row * BD + c0 + cdq);
                float4 nv = *(const float4*)(g_invL + row * Dn + c0 + cdq);
                uint32_t h01, m01, h23, m23;
                split_pair(v.x * nv.x, v.y * nv.y, h01, m01);
                split_pair(v.z * nv.z, v.w * nv.w, h23, m23);
                *(uint2*)(pl + AH_OFF + e) = make_uint2(h01, h23);
                *(uint2*)(pl + AM_OFF + e) = make_uint2(m01, m23);
            }
            if (row < rl) {
                float4 v  = *(const float4*)(rbase + (size_t)row * BD + c0 + cdq);
                float4 nv = *(const float4*)(g_invR + row * Dn + c0 + cdq);
                uint32_t h01, m01, h23, m23;
                split_pair(v.x * nv.x, v.y * nv.y, h01, m01);
                split_pair(v.z * nv.z, v.w * nv.w, h23, m23);
                *(uint2*)(pl + BH_OFF + e) = make_uint2(h01, h23);
                *(uint2*)(pl + BM_OFF + e) = make_uint2(m01, m23);
            }
        }
        __syncthreads();

        if (act0) {
#pragma unroll
            for (int ks = 0; ks < KCg / 16; ks++) {
                const int k0 = ks * 16;
                wmma::fragment<wmma::matrix_a, 16, 16, 16, __nv_bfloat16,
                               wmma::row_major> ah[2], am[2];
                {
                    const int r0 = 32 * warp_m;
                    wmma::load_matrix_sync(ah[0], pl + AH_OFF + r0 * PLDb + k0, PLDb);
                    wmma::load_matrix_sync(am[0], pl + AM_OFF + r0 * PLDb + k0, PLDb);
                    if (act1) {
                        wmma::load_matrix_sync(ah[1], pl + AH_OFF + (r0 + 16) * PLDb + k0, PLDb);
                        wmma::load_matrix_sync(am[1], pl + AM_OFF + (r0 + 16) * PLDb + k0, PLDb);
                    }
                }
#pragma unroll
                for (int n = 0; n < 4; n++) {
                    const int n0 = 64 * warp_n + 16 * n;
                    if (n0 >= rl) continue;                 // B tile fully masked
                    wmma::fragment<wmma::matrix_b, 16, 16, 16, __nv_bfloat16,
                                   wmma::col_major> bh, bm;
                    wmma::load_matrix_sync(bh, pl + BH_OFF + n0 * PLDb + k0, PLDb);
                    wmma::load_matrix_sync(bm, pl + BM_OFF + n0 * PLDb + k0, PLDb);
                    wmma::mma_sync(cf[0][n], ah[0], bh, cf[0][n]);
                    wmma::mma_sync(cf[0][n], am[0], bh, cf[0][n]);
                    wmma::mma_sync(cf[0][n], ah[0], bm, cf[0][n]);
                    if (act1) {
                        wmma::mma_sync(cf[1][n], ah[1], bh, cf[1][n]);
                        wmma::mma_sync(cf[1][n], am[1], bh, cf[1][n]);
                        wmma::mma_sync(cf[1][n], ah[1], bm, cf[1][n]);
                    }
                }
            }
        }
        __syncthreads();
    }

    // -------- epilogue: fragments -> att, then mask in place --------
#pragma unroll
    for (int i = 0; i < 2; i++)
#pragma unroll
        for (int n = 0; n < 4; n++) {
            const int r0 = 32 * warp_m + 16 * i;
            const int n0 = 64 * warp_n + 16 * n;
            wmma::store_matrix_sync(att + r0 * ATTLD + n0, cf[i][n], ATTLD,
                                    wmma::mem_row_major);
        }
    __syncthreads();

#pragma unroll
    for (int j = 0; j < 16; j++) {
        int i4  = tid + 256 * j;          // 4096 float4 = 128 x 128
        int row = i4 >> 5;
        int c4  = (i4 & 31) << 2;
        float4* p = (float4*)(att + row * ATTLD + c4);
        float4 v = *p;
        float lmv = lm[row];
        v.x *= lmv * rm[c4 + 0];
        v.y *= lmv * rm[c4 + 1];
        v.z *= lmv * rm[c4 + 2];
        v.w *= lmv * rm[c4 + 3];
        *p = v;
    }
    __syncthreads();

    // -------- reductions with fp64 near-tie refinement --------
    for (int r8 = 0; r8 < 16; r8++) {
        int row = wid * 16 + r8;
        float best = att[row * ATTLD + lane];
        int   bi   = lane;
#pragma unroll
        for (int m = 1; m < 4; m++) {
            float v = att[row * ATTLD + lane + 32 * m];
            if (v > best) { best = v; bi = lane + 32 * m; }
        }
#pragma unroll
        for (int off = 16; off; off >>= 1) {
            float ov = __shfl_xor_sync(0xffffffffu, best, off);
            int   oi = __shfl_xor_sync(0xffffffffu, bi,   off);
            if (ov > best || (ov == best && oi < bi)) { best = ov; bi = oi; }
        }
        float thr = best - EPS;
        int cnt = 0;
#pragma unroll
        for (int m = 0; m < 4; m++) {
            float v = att[row * ATTLD + m * 32 + lane];
            cnt += __popc(__ballot_sync(0xffffffffu, v >= thr));
        }
        int fi = bi;
        if (cnt >= 2) {
            bool zmode = (best == 0.0f);
            double bbest;
            int    bbi;
            if (zmode) { bbest = 0.0; bbi = bi; }
            else       { bbest = -1e300; bbi = -1; }
#pragma unroll
            for (int m = 0; m < 4; m++) {
                float v = att[row * ATTLD + m * 32 + lane];
                bool near = (v >= thr) && (!zmode || v != 0.0f);
                unsigned bal = __ballot_sync(0xffffffffu, near);
                while (bal) {
                    int ln = __ffs(bal) - 1;
                    bal &= bal - 1;
                    int cand = m * 32 + ln;
                    bool masked = (lm[row] == 0.0f) || (rm[cand] == 0.0f);
                    double val = masked ? 0.0 : dot64(left, right, row, cand, b);
                    if (val > bbest || (val == bbest && cand < bbi)) { bbest = val; bbi = cand; }
                }
            }
            fi = bbi;
        }
        if (lane == 0) {
            out[LS_OFF + (size_t)row * Bn + b] = att[row * ATTLD + fi];
            g_lidx[b * Ln + row] = fi;
        }
    }

    for (int c8 = 0; c8 < 16; c8++) {
        int col = wid * 16 + c8;
        float best = att[lane * ATTLD + col];
        int   bi   = lane;
#pragma unroll
        for (int m = 1; m < 4; m++) {
            float v = att[(lane + 32 * m) * ATTLD + col];
            if (v > best) { best = v; bi = lane + 32 * m; }
        }
#pragma unroll
        for (int off = 16; off; off >>= 1) {
            float ov = __shfl_xor_sync(0xffffffffu, best, off);
            int   oi = __shfl_xor_sync(0xffffffffu, bi,   off);
            if (ov > best || (ov == best && oi < bi)) { best = ov; bi = oi; }
        }
        float thr = best - EPS;
        int cnt = 0;
#pragma unroll
        for (int m = 0; m < 4; m++) {
            float v = att[(m * 32 + lane) * ATTLD + col];
            cnt += __popc(__ballot_sync(0xffffffffu, v >= thr));
        }
        int fi = bi;
        if (cnt >= 2) {
            bool zmode = (best == 0.0f);
            double bbest;
            int    bbi;
            if (zmode) { bbest = 0.0; bbi = bi; }
            else       { bbest = -1e300; bbi = -1; }
#pragma unroll
            for (int m = 0; m < 4; m++) {
                float v = att[(m * 32 + lane) * ATTLD + col];
                bool near = (v >= thr) && (!zmode || v != 0.0f);
                unsigned bal = __ballot_sync(0xffffffffu, near);
                while (bal) {
                    int ln = __ffs(bal) - 1;
                    bal &= bal - 1;
                    int cand = m * 32 + ln;
                    bool masked = (lm[cand] == 0.0f) || (rm[col] == 0.0f);
                    double val = masked ? 0.0 : dot64(left, right, cand, col, b);
                    if (val > bbest || (val == bbest && cand < bbi)) { bbest = val; bbi = cand; }
                }
            }
            fi = bbi;
        }
        if (lane == 0) {
            out[RS_OFF + (size_t)col * Bn + b] = att[fi * ATTLD + col];
            g_ridx[b * Rn + col] = fi;
        }
    }
}

// ---------------------------------------------------------------------------
// Kernel 3: difference gathers (R8 version — split sides, full thread count).
// ---------------------------------------------------------------------------
__global__ __launch_bounds__(256) void diff_kernel(const float* __restrict__ left,
                                                   const int*   __restrict__ llen,
                                                   const float* __restrict__ right,
                                                   const int*   __restrict__ rlen,
                                                   float*       __restrict__ out) {
    const int PER_SIDE = Ln * Bn * ROW4;
    int g = blockIdx.x * blockDim.x + threadIdx.x;
    bool isL = (g < PER_SIDE);
    int i4 = isL ? g : g - PER_SIDE;

    int l   = i4 / (Bn * ROW4);
    int rem = i4 - l * (Bn * ROW4);
    int b   = rem / ROW4;
    int dq  = rem - b * ROW4;

    const float4* l4 = (const float4*)left;
    const float4* r4 = (const float4*)right;

    float4 res = make_float4(0.f, 0.f, 0.f, 0.f);
    if (isL) {
        if (l < llen[b]) {
            int idx = g_lidx[b * Ln + l];
            float4 a = l4[i4];
            float4 c = r4[(size_t)idx * BD4 + (size_t)b * ROW4 + dq];
            res = make_float4(a.x - c.x, a.y - c.y, a.z - c.z, a.w - c.w);
        }
        ((float4*)(out + LD_OFF))[i4] = res;
    } else {
        if (l < rlen[b]) {
            int idx = g_ridx[b * Rn + l];
            float4 a = r4[i4];
            float4 c = l4[(size_t)idx * BD4 + (size_t)b * ROW4 + dq];
            res = make_float4(a.x - c.x, a.y - c.y, a.z - c.z, a.w - c.w);
        }
        ((float4*)(out + RD_OFF))[i4] = res;
    }
}

// ---------------------------------------------------------------------------
extern "C" void kernel_launch(void* const* d_in, const int* in_sizes, int n_in,
                              void* d_out, int out_size) {
    (void)in_sizes; (void)n_in; (void)out_size;
    const float* left  = (const float*)d_in[0];
    const int*   llen  = (const int*)d_in[1];
    const float* right = (const float*)d_in[2];
    const int*   rlen  = (const int*)d_in[3];
    float* out = (float*)d_out;

    cudaFuncSetAttribute(main_kernel, cudaFuncAttributeMaxDynamicSharedMemorySize,
                         DSMEM_BYTES);

    norms_kernel<<<(2 * Ln * Dn) / 256, 256>>>(left, right);
    main_kernel<<<Bn, 256, DSMEM_BYTES>>>(left, llen, right, rlen, out);

    const int PER_SIDE = Ln * Bn * ROW4;
    diff_kernel<<<(2 * PER_SIDE) / 256, 256>>>(left, llen, right, rlen, out);
}

// round 12
// speedup vs baseline: 1.0492x; 1.0005x over previous
#include <cuda_runtime.h>
#include <cuda_bf16.h>
#include <mma.h>
#include <cstdint>

using namespace nvcuda;

// Problem constants
#define Bn 512
#define Dn 768
#define Ln 128
#define Rn 128
#define BD (Bn * Dn)
#define BD4 (BD / 4)
#define ROW4 (Dn / 4)        // 192
#define KCg 64               // fp32 K-cols per chunk (bf16 K=64)
#define NCHUNK (Dn / KCg)    // 12
#define PLDb 72              // bf16 plane leading dim (elements), mult of 8
#define ATTLD 132            // att leading dim (floats)
#define EPS 2e-4f            // covers worst-case bf16-split error with margin

// Output offsets (floats), reference tuple order
#define LD_OFF 0ull
#define RD_OFF 50331648ull
#define LM_OFF 100663296ull
#define RM_OFF 100728832ull
#define LS_OFF 100794368ull
#define RS_OFF 100859904ull

// bf16 plane element offsets
#define AH_OFF 0
#define AM_OFF (128 * PLDb)
#define BH_OFF (2 * 128 * PLDb)
#define BM_OFF (3 * 128 * PLDb)
#define PLANE_ELEMS (4 * 128 * PLDb)
#define DSMEM_BYTES (PLANE_ELEMS * 2)      // 73728 B (>= att 128*132*4 = 67584)

// Scratch
__device__ float  g_invL[Ln * Dn];
__device__ float  g_invR[Rn * Dn];
__device__ double g_inv64L[Ln * Dn];
__device__ double g_inv64R[Rn * Dn];

// fp32 pair -> (hi, mid) bf16x2: lower half = a (even col), upper = b (odd col)
__device__ __forceinline__ void split_pair(float a, float b, uint32_t& h, uint32_t& m) {
    asm("cvt.rn.bf16x2.f32 %0, %1, %2;" : "=r"(h) : "f"(b), "f"(a));
    float ha = __uint_as_float(h << 16);
    float hb = __uint_as_float(h & 0xffff0000u);
    float ra = a - ha, rb = b - hb;
    asm("cvt.rn.bf16x2.f32 %0, %1, %2;" : "=r"(m) : "f"(rb), "f"(ra));
}

// ---------------------------------------------------------------------------
// Kernel 1: inv_n[l,d] = 1/sqrt(sum_b x[l,b,d]^2), fp64 accumulation.
// (R8 version — measured 68 us @ 75% DRAM; do not touch.)
// ---------------------------------------------------------------------------
__global__ __launch_bounds__(256) void norms_kernel(const float* __restrict__ left,
                                                    const float* __restrict__ right) {
    int gid = blockIdx.x * blockDim.x + threadIdx.x;
    const int LD = Ln * Dn;
    const float* src;
    float* dst32;
    double* dst64;
    int idx;
    if (gid < LD) { src = left;  dst32 = g_invL; dst64 = g_inv64L; idx = gid; }
    else          { src = right; dst32 = g_invR; dst64 = g_inv64R; idx = gid - LD; }
    int l = idx / Dn;
    int d = idx - l * Dn;
    const float* p = src + (size_t)l * BD + d;
    double acc = 0.0;
#pragma unroll 8
    for (int b = 0; b < Bn; b++) {
        double v = (double)p[(size_t)b * Dn];
        acc += v * v;
    }
    double inv = 1.0 / sqrt(acc);
    dst64[idx] = inv;
    dst32[idx] = (float)inv;
}

// ---------------------------------------------------------------------------
// Warp-collective fp64 normalized dot (ground truth for near-ties)
// ---------------------------------------------------------------------------
__device__ __forceinline__ double dot64(const float* __restrict__ left,
                                        const float* __restrict__ right,
                                        int l, int r, int b) {
    const int lane = threadIdx.x & 31;
    const float*  lp = left  + (size_t)l * BD + (size_t)b * Dn;
    const float*  rp = right + (size_t)r * BD + (size_t)b * Dn;
    const double* il = g_inv64L + l * Dn;
    const double* ir = g_inv64R + r * Dn;
    double acc = 0.0;
    for (int d = lane; d < Dn; d += 32)
        acc += (double)lp[d] * (double)rp[d] * il[d] * ir[d];
#pragma unroll
    for (int off = 16; off; off >>= 1)
        acc += __shfl_xor_sync(0xffffffffu, acc, off);
    return acc;
}

// ---------------------------------------------------------------------------
// Kernel 2: one CTA per batch. R8's bf16 2-plane 3-product wmma GEMM +
// max/argmax, with the diff gathers fused at the tail (indices via smem).
// ---------------------------------------------------------------------------
__global__ __launch_bounds__(256, 2) void main_kernel(const float* __restrict__ left,
                                                      const int*   __restrict__ llen,
                                                      const float* __restrict__ right,
                                                      const int*   __restrict__ rlen,
                                                      float*       __restrict__ out) {
    const int b    = blockIdx.x;
    const int tid  = threadIdx.x;
    const int wid  = tid >> 5;
    const int lane = tid & 31;
    const int warp_m = wid >> 1;   // 0..3: C rows [32*warp_m, +32)
    const int warp_n = wid & 1;    // 0..1: C cols [64*warp_n, +64)

    __shared__ float lm[Ln];
    __shared__ float rm[Rn];
    __shared__ int   lidx[Ln];
    __shared__ int   ridx[Rn];

    extern __shared__ float smem[];
    __nv_bfloat16* pl = (__nv_bfloat16*)smem;   // bf16 planes
    float* att = smem;                           // aliases planes after GEMM

    const int ll = llen[b];
    const int rl = rlen[b];

    // -------- masks --------
    if (tid < 128) {
        float lmv = (tid < ll) ? 1.0f : 0.0f;
        float rmv = (tid < rl) ? 1.0f : 0.0f;
        lm[tid] = lmv;
        rm[tid] = rmv;
        out[LM_OFF + (size_t)b * Ln + tid] = lmv;
        out[RM_OFF + (size_t)b * Rn + tid] = rmv;
    }

    // -------- GEMM: bf16 hi/mid, products hh + hm + mh --------
    wmma::fragment<wmma::accumulator, 16, 16, 16, float> cf[2][4];
#pragma unroll
    for (int i = 0; i < 2; i++)
#pragma unroll
        for (int j = 0; j < 4; j++) wmma::fill_fragment(cf[i][j], 0.0f);

    const float* lbase = left  + (size_t)b * Dn;
    const float* rbase = right + (size_t)b * Dn;
    const float4 z4 = make_float4(0.f, 0.f, 0.f, 0.f);

    const bool act0 = (32 * warp_m      < ll);
    const bool act1 = (32 * warp_m + 16 < ll);

    for (int c = 0; c < NCHUNK; c++) {
        const int c0 = c * KCg;

        // convert both matrices into hi/mid bf16 planes (R8: operand-level
        // predication — masked rows produce zeros, loads stay batched)
#pragma unroll
        for (int j = 0; j < 8; j++) {
            int i   = tid + 256 * j;       // 0..2047
            int row = i >> 4;              // 0..127
            int dq  = (i & 15) << 2;       // 0..60
            // A
            {
                float4 v  = (row < ll) ? *(const float4*)(lbase + (size_t)row * BD + c0 + dq) : z4;
                float4 nv = *(const float4*)(g_invL + row * Dn + c0 + dq);
                uint32_t h01, m01, h23, m23;
                split_pair(v.x * nv.x, v.y * nv.y, h01, m01);
                split_pair(v.z * nv.z, v.w * nv.w, h23, m23);
                int e = row * PLDb + dq;
                *(uint2*)(pl + AH_OFF + e) = make_uint2(h01, h23);
                *(uint2*)(pl + AM_OFF + e) = make_uint2(m01, m23);
            }
            // B
            {
                float4 v  = (row < rl) ? *(const float4*)(rbase + (size_t)row * BD + c0 + dq) : z4;
                float4 nv = *(const float4*)(g_invR + row * Dn + c0 + dq);
                uint32_t h01, m01, h23, m23;
                split_pair(v.x * nv.x, v.y * nv.y, h01, m01);
                split_pair(v.z * nv.z, v.w * nv.w, h23, m23);
                int e = row * PLDb + dq;
                *(uint2*)(pl + BH_OFF + e) = make_uint2(h01, h23);
                *(uint2*)(pl + BM_OFF + e) = make_uint2(m01, m23);
            }
        }
        __syncthreads();

        if (act0) {
#pragma unroll
            for (int ks = 0; ks < KCg / 16; ks++) {
                const int k0 = ks * 16;
                wmma::fragment<wmma::matrix_a, 16, 16, 16, __nv_bfloat16,
                               wmma::row_major> ah[2], am[2];
                {
                    const int r0 = 32 * warp_m;
                    wmma::load_matrix_sync(ah[0], pl + AH_OFF + r0 * PLDb + k0, PLDb);
                    wmma::load_matrix_sync(am[0], pl + AM_OFF + r0 * PLDb + k0, PLDb);
                    if (act1) {
                        wmma::load_matrix_sync(ah[1], pl + AH_OFF + (r0 + 16) * PLDb + k0, PLDb);
                        wmma::load_matrix_sync(am[1], pl + AM_OFF + (r0 + 16) * PLDb + k0, PLDb);
                    }
                }
#pragma unroll
                for (int n = 0; n < 4; n++) {
                    const int n0 = 64 * warp_n + 16 * n;
                    if (n0 >= rl) continue;                 // B tile fully masked
                    wmma::fragment<wmma::matrix_b, 16, 16, 16, __nv_bfloat16,
                                   wmma::col_major> bh, bm;
                    wmma::load_matrix_sync(bh, pl + BH_OFF + n0 * PLDb + k0, PLDb);
                    wmma::load_matrix_sync(bm, pl + BM_OFF + n0 * PLDb + k0, PLDb);
                    wmma::mma_sync(cf[0][n], ah[0], bh, cf[0][n]);
                    wmma::mma_sync(cf[0][n], am[0], bh, cf[0][n]);
                    wmma::mma_sync(cf[0][n], ah[0], bm, cf[0][n]);
                    if (act1) {
                        wmma::mma_sync(cf[1][n], ah[1], bh, cf[1][n]);
                        wmma::mma_sync(cf[1][n], am[1], bh, cf[1][n]);
                        wmma::mma_sync(cf[1][n], ah[1], bm, cf[1][n]);
                    }
                }
            }
        }
        __syncthreads();
    }

    // -------- epilogue: fragments -> att, then mask in place --------
#pragma unroll
    for (int i = 0; i < 2; i++)
#pragma unroll
        for (int n = 0; n < 4; n++) {
            const int r0 = 32 * warp_m + 16 * i;
            const int n0 = 64 * warp_n + 16 * n;
            wmma::store_matrix_sync(att + r0 * ATTLD + n0, cf[i][n], ATTLD,
                                    wmma::mem_row_major);
        }
    __syncthreads();

#pragma unroll
    for (int j = 0; j < 16; j++) {
        int i4  = tid + 256 * j;          // 4096 float4 = 128 x 128
        int row = i4 >> 5;
        int c4  = (i4 & 31) << 2;
        float4* p = (float4*)(att + row * ATTLD + c4);
        float4 v = *p;
        float lmv = lm[row];
        v.x *= lmv * rm[c4 + 0];
        v.y *= lmv * rm[c4 + 1];
        v.z *= lmv * rm[c4 + 2];
        v.w *= lmv * rm[c4 + 3];
        *p = v;
    }
    __syncthreads();

    // -------- reductions with fp64 near-tie refinement --------
    for (int r8 = 0; r8 < 16; r8++) {
        int row = wid * 16 + r8;
        float best = att[row * ATTLD + lane];
        int   bi   = lane;
#pragma unroll
        for (int m = 1; m < 4; m++) {
            float v = att[row * ATTLD + lane + 32 * m];
            if (v > best) { best = v; bi = lane + 32 * m; }
        }
#pragma unroll
        for (int off = 16; off; off >>= 1) {
            float ov = __shfl_xor_sync(0xffffffffu, best, off);
            int   oi = __shfl_xor_sync(0xffffffffu, bi,   off);
            if (ov > best || (ov == best && oi < bi)) { best = ov; bi = oi; }
        }
        float thr = best - EPS;
        int cnt = 0;
#pragma unroll
        for (int m = 0; m < 4; m++) {
            float v = att[row * ATTLD + m * 32 + lane];
            cnt += __popc(__ballot_sync(0xffffffffu, v >= thr));
        }
        int fi = bi;
        if (cnt >= 2) {
            bool zmode = (best == 0.0f);
            double bbest;
            int    bbi;
            if (zmode) { bbest = 0.0; bbi = bi; }
            else       { bbest = -1e300; bbi = -1; }
#pragma unroll
            for (int m = 0; m < 4; m++) {
                float v = att[row * ATTLD + m * 32 + lane];
                bool near = (v >= thr) && (!zmode || v != 0.0f);
                unsigned bal = __ballot_sync(0xffffffffu, near);
                while (bal) {
                    int ln = __ffs(bal) - 1;
                    bal &= bal - 1;
                    int cand = m * 32 + ln;
                    bool masked = (lm[row] == 0.0f) || (rm[cand] == 0.0f);
                    double val = masked ? 0.0 : dot64(left, right, row, cand, b);
                    if (val > bbest || (val == bbest && cand < bbi)) { bbest = val; bbi = cand; }
                }
            }
            fi = bbi;
        }
        if (lane == 0) {
            out[LS_OFF + (size_t)row * Bn + b] = att[row * ATTLD + fi];
            lidx[row] = fi;
        }
    }

    for (int c8 = 0; c8 < 16; c8++) {
        int col = wid * 16 + c8;
        float best = att[lane * ATTLD + col];
        int   bi   = lane;
#pragma unroll
        for (int m = 1; m < 4; m++) {
            float v = att[(lane + 32 * m) * ATTLD + col];
            if (v > best) { best = v; bi = lane + 32 * m; }
        }
#pragma unroll
        for (int off = 16; off; off >>= 1) {
            float ov = __shfl_xor_sync(0xffffffffu, best, off);
            int   oi = __shfl_xor_sync(0xffffffffu, bi,   off);
            if (ov > best || (ov == best && oi < bi)) { best = ov; bi = oi; }
        }
        float thr = best - EPS;
        int cnt = 0;
#pragma unroll
        for (int m = 0; m < 4; m++) {
            float v = att[(m * 32 + lane) * ATTLD + col];
            cnt += __popc(__ballot_sync(0xffffffffu, v >= thr));
        }
        int fi = bi;
        if (cnt >= 2) {
            bool zmode = (best == 0.0f);
            double bbest;
            int    bbi;
            if (zmode) { bbest = 0.0; bbi = bi; }
            else       { bbest = -1e300; bbi = -1; }
#pragma unroll
            for (int m = 0; m < 4; m++) {
                float v = att[(m * 32 + lane) * ATTLD + col];
                bool near = (v >= thr) && (!zmode || v != 0.0f);
                unsigned bal = __ballot_sync(0xffffffffu, near);
                while (bal) {
                    int ln = __ffs(bal) - 1;
                    bal &= bal - 1;
                    int cand = m * 32 + ln;
                    bool masked = (lm[cand] == 0.0f) || (rm[col] == 0.0f);
                    double val = masked ? 0.0 : dot64(left, right, cand, col, b);
                    if (val > bbest || (val == bbest && cand < bbi)) { bbest = val; bbi = cand; }
                }
            }
            fi = bbi;
        }
        if (lane == 0) {
            out[RS_OFF + (size_t)col * Bn + b] = att[fi * ATTLD + col];
            ridx[col] = fi;
        }
    }
    __syncthreads();

    // -------- fused diff gathers (overlaps other CTAs' GEMM compute) --------
    const float4* l4 = (const float4*)left;
    const float4* r4 = (const float4*)right;
    float4* old4 = (float4*)(out + LD_OFF);
    float4* ord4 = (float4*)(out + RD_OFF);

    for (int i = tid; i < Ln * ROW4; i += 256) {
        int row = i / ROW4;
        int dq  = i - row * ROW4;
        size_t o = (size_t)row * BD4 + (size_t)b * ROW4 + dq;
        float4 res;
        if (lm[row] != 0.f) {
            float4 a = l4[o];
            float4 c = r4[(size_t)lidx[row] * BD4 + (size_t)b * ROW4 + dq];
            res = make_float4(a.x - c.x, a.y - c.y, a.z - c.z, a.w - c.w);
        } else {
            res = make_float4(0.f, 0.f, 0.f, 0.f);
        }
        old4[o] = res;
    }

    for (int i = tid; i < Rn * ROW4; i += 256) {
        int row = i / ROW4;
        int dq  = i - row * ROW4;
        size_t o = (size_t)row * BD4 + (size_t)b * ROW4 + dq;
        float4 res;
        if (rm[row] != 0.f) {
            float4 a = r4[o];
            float4 c = l4[(size_t)ridx[row] * BD4 + (size_t)b * ROW4 + dq];
            res = make_float4(a.x - c.x, a.y - c.y, a.z - c.z, a.w - c.w);
        } else {
            res = make_float4(0.f, 0.f, 0.f, 0.f);
        }
        ord4[o] = res;
    }
}

// ---------------------------------------------------------------------------
extern "C" void kernel_launch(void* const* d_in, const int* in_sizes, int n_in,
                              void* d_out, int out_size) {
    (void)in_sizes; (void)n_in; (void)out_size;
    const float* left  = (const float*)d_in[0];
    const int*   llen  = (const int*)d_in[1];
    const float* right = (const float*)d_in[2];
    const int*   rlen  = (const int*)d_in[3];
    float* out = (float*)d_out;

    cudaFuncSetAttribute(main_kernel, cudaFuncAttributeMaxDynamicSharedMemorySize,
                         DSMEM_BYTES);

    norms_kernel<<<(2 * Ln * Dn) / 256, 256>>>(left, right);
    main_kernel<<<Bn, 256, DSMEM_BYTES>>>(left, llen, right, rlen, out);
}

// round 13
// speedup vs baseline: 1.2889x; 1.2284x over previous
#include <cuda_runtime.h>
#include <cuda_bf16.h>
#include <mma.h>
#include <cstdint>

using namespace nvcuda;

// Problem constants
#define Bn 512
#define Dn 768
#define Ln 128
#define Rn 128
#define BD (Bn * Dn)
#define BD4 (BD / 4)
#define ROW4 (Dn / 4)        // 192
#define KCg 64               // fp32 K-cols per chunk (bf16 K=64)
#define NCHUNK (Dn / KCg)    // 12
#define PLDb 72              // bf16 plane leading dim (elements), mult of 8
#define ATTLD 132            // att leading dim (floats)
#define EPS 2e-4f            // covers worst-case bf16-split error with margin

// Output offsets (floats), reference tuple order
#define LD_OFF 0ull
#define RD_OFF 50331648ull
#define LM_OFF 100663296ull
#define RM_OFF 100728832ull
#define LS_OFF 100794368ull
#define RS_OFF 100859904ull

// bf16 plane element offsets
#define AH_OFF 0
#define AM_OFF (128 * PLDb)
#define BH_OFF (2 * 128 * PLDb)
#define BM_OFF (3 * 128 * PLDb)
#define PLANE_ELEMS (4 * 128 * PLDb)
#define DSMEM_BYTES (PLANE_ELEMS * 2)      // 73728 B (>= att 128*132*4 = 67584)

// Scratch
__device__ float  g_invL[Ln * Dn];
__device__ float  g_invR[Rn * Dn];
__device__ double g_inv64L[Ln * Dn];
__device__ double g_inv64R[Rn * Dn];
__device__ int    g_lidx[Bn * Ln];
__device__ int    g_ridx[Bn * Rn];

// fp32 pair -> (hi, mid) bf16x2: lower half = a (even col), upper = b (odd col)
__device__ __forceinline__ void split_pair(float a, float b, uint32_t& h, uint32_t& m) {
    asm("cvt.rn.bf16x2.f32 %0, %1, %2;" : "=r"(h) : "f"(b), "f"(a));
    float ha = __uint_as_float(h << 16);
    float hb = __uint_as_float(h & 0xffff0000u);
    float ra = a - ha, rb = b - hb;
    asm("cvt.rn.bf16x2.f32 %0, %1, %2;" : "=r"(m) : "f"(rb), "f"(ra));
}

// ---------------------------------------------------------------------------
// Kernel 1: inv_n[l,d] = 1/sqrt(sum_b x[l,b,d]^2), fp64 accumulation.
// R8 structure; unroll 16 for deeper MLP (was DRAM=73%, issue=16.8%).
// ---------------------------------------------------------------------------
__global__ __launch_bounds__(256) void norms_kernel(const float* __restrict__ left,
                                                    const float* __restrict__ right) {
    int gid = blockIdx.x * blockDim.x + threadIdx.x;
    const int LD = Ln * Dn;
    const float* src;
    float* dst32;
    double* dst64;
    int idx;
    if (gid < LD) { src = left;  dst32 = g_invL; dst64 = g_inv64L; idx = gid; }
    else          { src = right; dst32 = g_invR; dst64 = g_inv64R; idx = gid - LD; }
    int l = idx / Dn;
    int d = idx - l * Dn;
    const float* p = src + (size_t)l * BD + d;
    double acc = 0.0;
#pragma unroll 16
    for (int b = 0; b < Bn; b++) {
        double v = (double)p[(size_t)b * Dn];
        acc += v * v;
    }
    double inv = 1.0 / sqrt(acc);
    dst64[idx] = inv;
    dst32[idx] = (float)inv;
}

// ---------------------------------------------------------------------------
// Warp-collective fp64 normalized dot (ground truth for near-ties)
// ---------------------------------------------------------------------------
__device__ __forceinline__ double dot64(const float* __restrict__ left,
                                        const float* __restrict__ right,
                                        int l, int r, int b) {
    const int lane = threadIdx.x & 31;
    const float*  lp = left  + (size_t)l * BD + (size_t)b * Dn;
    const float*  rp = right + (size_t)r * BD + (size_t)b * Dn;
    const double* il = g_inv64L + l * Dn;
    const double* ir = g_inv64R + r * Dn;
    double acc = 0.0;
    for (int d = lane; d < Dn; d += 32)
        acc += (double)lp[d] * (double)rp[d] * il[d] * ir[d];
#pragma unroll
    for (int off = 16; off; off >>= 1)
        acc += __shfl_xor_sync(0xffffffffu, acc, off);
    return acc;
}

// ---------------------------------------------------------------------------
// Kernel 2: one CTA per batch. bf16 2-plane 3-product wmma GEMM + max/argmax.
// (exact R8 version — measured best)
// ---------------------------------------------------------------------------
__global__ __launch_bounds__(256, 2) void main_kernel(const float* __restrict__ left,
                                                      const int*   __restrict__ llen,
                                                      const float* __restrict__ right,
                                                      const int*   __restrict__ rlen,
                                                      float*       __restrict__ out) {
    const int b    = blockIdx.x;
    const int tid  = threadIdx.x;
    const int wid  = tid >> 5;
    const int lane = tid & 31;
    const int warp_m = wid >> 1;   // 0..3: C rows [32*warp_m, +32)
    const int warp_n = wid & 1;    // 0..1: C cols [64*warp_n, +64)

    __shared__ float lm[Ln];
    __shared__ float rm[Rn];

    extern __shared__ float smem[];
    __nv_bfloat16* pl = (__nv_bfloat16*)smem;   // bf16 planes
    float* att = smem;                           // aliases planes after GEMM

    const int ll = llen[b];
    const int rl = rlen[b];

    // -------- masks --------
    if (tid < 128) {
        float lmv = (tid < ll) ? 1.0f : 0.0f;
        float rmv = (tid < rl) ? 1.0f : 0.0f;
        lm[tid] = lmv;
        rm[tid] = rmv;
        out[LM_OFF + (size_t)b * Ln + tid] = lmv;
        out[RM_OFF + (size_t)b * Rn + tid] = rmv;
    }

    // -------- GEMM: bf16 hi/mid, products hh + hm + mh --------
    wmma::fragment<wmma::accumulator, 16, 16, 16, float> cf[2][4];
#pragma unroll
    for (int i = 0; i < 2; i++)
#pragma unroll
        for (int j = 0; j < 4; j++) wmma::fill_fragment(cf[i][j], 0.0f);

    const float* lbase = left  + (size_t)b * Dn;
    const float* rbase = right + (size_t)b * Dn;
    const float4 z4 = make_float4(0.f, 0.f, 0.f, 0.f);

    const bool act0 = (32 * warp_m      < ll);
    const bool act1 = (32 * warp_m + 16 < ll);

    for (int c = 0; c < NCHUNK; c++) {
        const int c0 = c * KCg;

        // convert both matrices into hi/mid bf16 planes (operand-level
        // predication — masked rows produce zeros, loads stay batched)
#pragma unroll
        for (int j = 0; j < 8; j++) {
            int i   = tid + 256 * j;       // 0..2047
            int row = i >> 4;              // 0..127
            int dq  = (i & 15) << 2;       // 0..60
            // A
            {
                float4 v  = (row < ll) ? *(const float4*)(lbase + (size_t)row * BD + c0 + dq) : z4;
                float4 nv = *(const float4*)(g_invL + row * Dn + c0 + dq);
                uint32_t h01, m01, h23, m23;
                split_pair(v.x * nv.x, v.y * nv.y, h01, m01);
                split_pair(v.z * nv.z, v.w * nv.w, h23, m23);
                int e = row * PLDb + dq;
                *(uint2*)(pl + AH_OFF + e) = make_uint2(h01, h23);
                *(uint2*)(pl + AM_OFF + e) = make_uint2(m01, m23);
            }
            // B
            {
                float4 v  = (row < rl) ? *(const float4*)(rbase + (size_t)row * BD + c0 + dq) : z4;
                float4 nv = *(const float4*)(g_invR + row * Dn + c0 + dq);
                uint32_t h01, m01, h23, m23;
                split_pair(v.x * nv.x, v.y * nv.y, h01, m01);
                split_pair(v.z * nv.z, v.w * nv.w, h23, m23);
                int e = row * PLDb + dq;
                *(uint2*)(pl + BH_OFF + e) = make_uint2(h01, h23);
                *(uint2*)(pl + BM_OFF + e) = make_uint2(m01, m23);
            }
        }
        __syncthreads();

        if (act0) {
#pragma unroll
            for (int ks = 0; ks < KCg / 16; ks++) {
                const int k0 = ks * 16;
                wmma::fragment<wmma::matrix_a, 16, 16, 16, __nv_bfloat16,
                               wmma::row_major> ah[2], am[2];
                {
                    const int r0 = 32 * warp_m;
                    wmma::load_matrix_sync(ah[0], pl + AH_OFF + r0 * PLDb + k0, PLDb);
                    wmma::load_matrix_sync(am[0], pl + AM_OFF + r0 * PLDb + k0, PLDb);
                    if (act1) {
                        wmma::load_matrix_sync(ah[1], pl + AH_OFF + (r0 + 16) * PLDb + k0, PLDb);
                        wmma::load_matrix_sync(am[1], pl + AM_OFF + (r0 + 16) * PLDb + k0, PLDb);
                    }
                }
#pragma unroll
                for (int n = 0; n < 4; n++) {
                    const int n0 = 64 * warp_n + 16 * n;
                    if (n0 >= rl) continue;                 // B tile fully masked
                    wmma::fragment<wmma::matrix_b, 16, 16, 16, __nv_bfloat16,
                                   wmma::col_major> bh, bm;
                    wmma::load_matrix_sync(bh, pl + BH_OFF + n0 * PLDb + k0, PLDb);
                    wmma::load_matrix_sync(bm, pl + BM_OFF + n0 * PLDb + k0, PLDb);
                    wmma::mma_sync(cf[0][n], ah[0], bh, cf[0][n]);
                    wmma::mma_sync(cf[0][n], am[0], bh, cf[0][n]);
                    wmma::mma_sync(cf[0][n], ah[0], bm, cf[0][n]);
                    if (act1) {
                        wmma::mma_sync(cf[1][n], ah[1], bh, cf[1][n]);
                        wmma::mma_sync(cf[1][n], am[1], bh, cf[1][n]);
                        wmma::mma_sync(cf[1][n], ah[1], bm, cf[1][n]);
                    }
                }
            }
        }
        __syncthreads();
    }

    // -------- epilogue: fragments -> att, then mask in place --------
#pragma unroll
    for (int i = 0; i < 2; i++)
#pragma unroll
        for (int n = 0; n < 4; n++) {
            const int r0 = 32 * warp_m + 16 * i;
            const int n0 = 64 * warp_n + 16 * n;
            wmma::store_matrix_sync(att + r0 * ATTLD + n0, cf[i][n], ATTLD,
                                    wmma::mem_row_major);
        }
    __syncthreads();

#pragma unroll
    for (int j = 0; j < 16; j++) {
        int i4  = tid + 256 * j;          // 4096 float4 = 128 x 128
        int row = i4 >> 5;
        int c4  = (i4 & 31) << 2;
        float4* p = (float4*)(att + row * ATTLD + c4);
        float4 v = *p;
        float lmv = lm[row];
        v.x *= lmv * rm[c4 + 0];
        v.y *= lmv * rm[c4 + 1];
        v.z *= lmv * rm[c4 + 2];
        v.w *= lmv * rm[c4 + 3];
        *p = v;
    }
    __syncthreads();

    // -------- reductions with fp64 near-tie refinement --------
    for (int r8 = 0; r8 < 16; r8++) {
        int row = wid * 16 + r8;
        float best = att[row * ATTLD + lane];
        int   bi   = lane;
#pragma unroll
        for (int m = 1; m < 4; m++) {
            float v = att[row * ATTLD + lane + 32 * m];
            if (v > best) { best = v; bi = lane + 32 * m; }
        }
#pragma unroll
        for (int off = 16; off; off >>= 1) {
            float ov = __shfl_xor_sync(0xffffffffu, best, off);
            int   oi = __shfl_xor_sync(0xffffffffu, bi,   off);
            if (ov > best || (ov == best && oi < bi)) { best = ov; bi = oi; }
        }
        float thr = best - EPS;
        int cnt = 0;
#pragma unroll
        for (int m = 0; m < 4; m++) {
            float v = att[row * ATTLD + m * 32 + lane];
            cnt += __popc(__ballot_sync(0xffffffffu, v >= thr));
        }
        int fi = bi;
        if (cnt >= 2) {
            bool zmode = (best == 0.0f);
            double bbest;
            int    bbi;
            if (zmode) { bbest = 0.0; bbi = bi; }
            else       { bbest = -1e300; bbi = -1; }
#pragma unroll
            for (int m = 0; m < 4; m++) {
                float v = att[row * ATTLD + m * 32 + lane];
                bool near = (v >= thr) && (!zmode || v != 0.0f);
                unsigned bal = __ballot_sync(0xffffffffu, near);
                while (bal) {
                    int ln = __ffs(bal) - 1;
                    bal &= bal - 1;
                    int cand = m * 32 + ln;
                    bool masked = (lm[row] == 0.0f) || (rm[cand] == 0.0f);
                    double val = masked ? 0.0 : dot64(left, right, row, cand, b);
                    if (val > bbest || (val == bbest && cand < bbi)) { bbest = val; bbi = cand; }
                }
            }
            fi = bbi;
        }
        if (lane == 0) {
            out[LS_OFF + (size_t)row * Bn + b] = att[row * ATTLD + fi];
            g_lidx[b * Ln + row] = fi;
        }
    }

    for (int c8 = 0; c8 < 16; c8++) {
        int col = wid * 16 + c8;
        float best = att[lane * ATTLD + col];
        int   bi   = lane;
#pragma unroll
        for (int m = 1; m < 4; m++) {
            float v = att[(lane + 32 * m) * ATTLD + col];
            if (v > best) { best = v; bi = lane + 32 * m; }
        }
#pragma unroll
        for (int off = 16; off; off >>= 1) {
            float ov = __shfl_xor_sync(0xffffffffu, best, off);
            int   oi = __shfl_xor_sync(0xffffffffu, bi,   off);
            if (ov > best || (ov == best && oi < bi)) { best = ov; bi = oi; }
        }
        float thr = best - EPS;
        int cnt = 0;
#pragma unroll
        for (int m = 0; m < 4; m++) {
            float v = att[(m * 32 + lane) * ATTLD + col];
            cnt += __popc(__ballot_sync(0xffffffffu, v >= thr));
        }
        int fi = bi;
        if (cnt >= 2) {
            bool zmode = (best == 0.0f);
            double bbest;
            int    bbi;
            if (zmode) { bbest = 0.0; bbi = bi; }
            else       { bbest = -1e300; bbi = -1; }
#pragma unroll
            for (int m = 0; m < 4; m++) {
                float v = att[(m * 32 + lane) * ATTLD + col];
                bool near = (v >= thr) && (!zmode || v != 0.0f);
                unsigned bal = __ballot_sync(0xffffffffu, near);
                while (bal) {
                    int ln = __ffs(bal) - 1;
                    bal &= bal - 1;
                    int cand = m * 32 + ln;
                    bool masked = (lm[cand] == 0.0f) || (rm[col] == 0.0f);
                    double val = masked ? 0.0 : dot64(left, right, cand, col, b);
                    if (val > bbest || (val == bbest && cand < bbi)) { bbest = val; bbi = cand; }
                }
            }
            fi = bbi;
        }
        if (lane == 0) {
            out[RS_OFF + (size_t)col * Bn + b] = att[fi * ATTLD + col];
            g_ridx[b * Rn + col] = fi;
        }
    }
}

// ---------------------------------------------------------------------------
// Kernel 3: difference gathers, pure streaming at full occupancy.
// (exact R8 version — split sides, full thread count)
// ---------------------------------------------------------------------------
__global__ __launch_bounds__(256) void diff_kernel(const float* __restrict__ left,
                                                   const int*   __restrict__ llen,
                                                   const float* __restrict__ right,
                                                   const int*   __restrict__ rlen,
                                                   float*       __restrict__ out) {
    const int PER_SIDE = Ln * Bn * ROW4;
    int g = blockIdx.x * blockDim.x + threadIdx.x;
    bool isL = (g < PER_SIDE);
    int i4 = isL ? g : g - PER_SIDE;

    int l   = i4 / (Bn * ROW4);
    int rem = i4 - l * (Bn * ROW4);
    int b   = rem / ROW4;
    int dq  = rem - b * ROW4;

    const float4* l4 = (const float4*)left;
    const float4* r4 = (const float4*)right;

    float4 res = make_float4(0.f, 0.f, 0.f, 0.f);
    if (isL) {
        if (l < llen[b]) {
            int idx = g_lidx[b * Ln + l];
            float4 a = l4[i4];
            float4 c = r4[(size_t)idx * BD4 + (size_t)b * ROW4 + dq];
            res = make_float4(a.x - c.x, a.y - c.y, a.z - c.z, a.w - c.w);
        }
        ((float4*)(out + LD_OFF))[i4] = res;
    } else {
        if (l < rlen[b]) {
            int idx = g_ridx[b * Rn + l];
            float4 a = r4[i4];
            float4 c = l4[(size_t)idx * BD4 + (size_t)b * ROW4 + dq];
            res = make_float4(a.x - c.x, a.y - c.y, a.z - c.z, a.w - c.w);
        }
        ((float4*)(out + RD_OFF))[i4] = res;
    }
}

// ---------------------------------------------------------------------------
extern "C" void kernel_launch(void* const* d_in, const int* in_sizes, int n_in,
                              void* d_out, int out_size) {
    (void)in_sizes; (void)n_in; (void)out_size;
    const float* left  = (const float*)d_in[0];
    const int*   llen  = (const int*)d_in[1];
    const float* right = (const float*)d_in[2];
    const int*   rlen  = (const int*)d_in[3];
    float* out = (float*)d_out;

    cudaFuncSetAttribute(main_kernel, cudaFuncAttributeMaxDynamicSharedMemorySize,
                         DSMEM_BYTES);

    norms_kernel<<<(2 * Ln * Dn) / 256, 256>>>(left, right);
    main_kernel<<<Bn, 256, DSMEM_BYTES>>>(left, llen, right, rlen, out);

    const int PER_SIDE = Ln * Bn * ROW4;
    diff_kernel<<<(2 * PER_SIDE) / 256, 256>>>(left, llen, right, rlen, out);
}

// round 14
// speedup vs baseline: 1.3313x; 1.0329x over previous
#include <cuda_runtime.h>
#include <cuda_bf16.h>
#include <mma.h>
#include <cstdint>

using namespace nvcuda;

// Problem constants
#define Bn 512
#define Dn 768
#define Ln 128
#define Rn 128
#define BD (Bn * Dn)
#define BD4 (BD / 4)
#define ROW4 (Dn / 4)        // 192
#define KCg 64               // fp32 K-cols per chunk (bf16 K=64)
#define NCHUNK (Dn / KCg)    // 12
#define PLDb 72              // bf16 plane leading dim (elements), mult of 8
#define ATTLD 132            // att leading dim (floats)
#define EPS 2e-4f            // covers worst-case bf16-split error with margin

// Output offsets (floats), reference tuple order
#define LD_OFF 0ull
#define RD_OFF 50331648ull
#define LM_OFF 100663296ull
#define RM_OFF 100728832ull
#define LS_OFF 100794368ull
#define RS_OFF 100859904ull

// bf16 plane element offsets
#define AH_OFF 0
#define AM_OFF (128 * PLDb)
#define BH_OFF (2 * 128 * PLDb)
#define BM_OFF (3 * 128 * PLDb)
#define PLANE_ELEMS (4 * 128 * PLDb)
#define DSMEM_BYTES (PLANE_ELEMS * 2)      // 73728 B (>= att 128*132*4 = 67584)

// Scratch
__device__ float  g_invL[Ln * Dn];
__device__ float  g_invR[Rn * Dn];
__device__ double g_inv64L[Ln * Dn];
__device__ double g_inv64R[Rn * Dn];
__device__ int    g_lidx[Bn * Ln];
__device__ int    g_ridx[Bn * Rn];

// fp32 pair -> (hi, mid) bf16x2: lower half = a (even col), upper = b (odd col)
__device__ __forceinline__ void split_pair(float a, float b, uint32_t& h, uint32_t& m) {
    asm("cvt.rn.bf16x2.f32 %0, %1, %2;" : "=r"(h) : "f"(b), "f"(a));
    float ha = __uint_as_float(h << 16);
    float hb = __uint_as_float(h & 0xffff0000u);
    float ra = a - ha, rb = b - hb;
    asm("cvt.rn.bf16x2.f32 %0, %1, %2;" : "=r"(m) : "f"(rb), "f"(ra));
}

// ---------------------------------------------------------------------------
// Kernel 1: inv_n[l,d] = 1/sqrt(sum_b x[l,b,d]^2), fp64 accumulation.
// (exact R8 version — measured 68 us @ 75% DRAM; unroll 8 is the plateau)
// ---------------------------------------------------------------------------
__global__ __launch_bounds__(256) void norms_kernel(const float* __restrict__ left,
                                                    const float* __restrict__ right) {
    int gid = blockIdx.x * blockDim.x + threadIdx.x;
    const int LD = Ln * Dn;
    const float* src;
    float* dst32;
    double* dst64;
    int idx;
    if (gid < LD) { src = left;  dst32 = g_invL; dst64 = g_inv64L; idx = gid; }
    else          { src = right; dst32 = g_invR; dst64 = g_inv64R; idx = gid - LD; }
    int l = idx / Dn;
    int d = idx - l * Dn;
    const float* p = src + (size_t)l * BD + d;
    double acc = 0.0;
#pragma unroll 8
    for (int b = 0; b < Bn; b++) {
        double v = (double)p[(size_t)b * Dn];
        acc += v * v;
    }
    double inv = 1.0 / sqrt(acc);
    dst64[idx] = inv;
    dst32[idx] = (float)inv;
}

// ---------------------------------------------------------------------------
// Warp-collective fp64 normalized dot (ground truth for near-ties)
// ---------------------------------------------------------------------------
__device__ __forceinline__ double dot64(const float* __restrict__ left,
                                        const float* __restrict__ right,
                                        int l, int r, int b) {
    const int lane = threadIdx.x & 31;
    const float*  lp = left  + (size_t)l * BD + (size_t)b * Dn;
    const float*  rp = right + (size_t)r * BD + (size_t)b * Dn;
    const double* il = g_inv64L + l * Dn;
    const double* ir = g_inv64R + r * Dn;
    double acc = 0.0;
    for (int d = lane; d < Dn; d += 32)
        acc += (double)lp[d] * (double)rp[d] * il[d] * ir[d];
#pragma unroll
    for (int off = 16; off; off >>= 1)
        acc += __shfl_xor_sync(0xffffffffu, acc, off);
    return acc;
}

// ---------------------------------------------------------------------------
// Kernel 2: one CTA per batch. bf16 2-plane 3-product wmma GEMM + max/argmax.
// (exact R8 version — measured best)
// ---------------------------------------------------------------------------
__global__ __launch_bounds__(256, 2) void main_kernel(const float* __restrict__ left,
                                                      const int*   __restrict__ llen,
                                                      const float* __restrict__ right,
                                                      const int*   __restrict__ rlen,
                                                      float*       __restrict__ out) {
    const int b    = blockIdx.x;
    const int tid  = threadIdx.x;
    const int wid  = tid >> 5;
    const int lane = tid & 31;
    const int warp_m = wid >> 1;   // 0..3: C rows [32*warp_m, +32)
    const int warp_n = wid & 1;    // 0..1: C cols [64*warp_n, +64)

    __shared__ float lm[Ln];
    __shared__ float rm[Rn];

    extern __shared__ float smem[];
    __nv_bfloat16* pl = (__nv_bfloat16*)smem;   // bf16 planes
    float* att = smem;                           // aliases planes after GEMM

    const int ll = llen[b];
    const int rl = rlen[b];

    // -------- masks --------
    if (tid < 128) {
        float lmv = (tid < ll) ? 1.0f : 0.0f;
        float rmv = (tid < rl) ? 1.0f : 0.0f;
        lm[tid] = lmv;
        rm[tid] = rmv;
        out[LM_OFF + (size_t)b * Ln + tid] = lmv;
        out[RM_OFF + (size_t)b * Rn + tid] = rmv;
    }

    // -------- GEMM: bf16 hi/mid, products hh + hm + mh --------
    wmma::fragment<wmma::accumulator, 16, 16, 16, float> cf[2][4];
#pragma unroll
    for (int i = 0; i < 2; i++)
#pragma unroll
        for (int j = 0; j < 4; j++) wmma::fill_fragment(cf[i][j], 0.0f);

    const float* lbase = left  + (size_t)b * Dn;
    const float* rbase = right + (size_t)b * Dn;
    const float4 z4 = make_float4(0.f, 0.f, 0.f, 0.f);

    const bool act0 = (32 * warp_m      < ll);
    const bool act1 = (32 * warp_m + 16 < ll);

    for (int c = 0; c < NCHUNK; c++) {
        const int c0 = c * KCg;

        // convert both matrices into hi/mid bf16 planes (operand-level
        // predication — masked rows produce zeros, loads stay batched)
#pragma unroll
        for (int j = 0; j < 8; j++) {
            int i   = tid + 256 * j;       // 0..2047
            int row = i >> 4;              // 0..127
            int dq  = (i & 15) << 2;       // 0..60
            // A
            {
                float4 v  = (row < ll) ? *(const float4*)(lbase + (size_t)row * BD + c0 + dq) : z4;
                float4 nv = *(const float4*)(g_invL + row * Dn + c0 + dq);
                uint32_t h01, m01, h23, m23;
                split_pair(v.x * nv.x, v.y * nv.y, h01, m01);
                split_pair(v.z * nv.z, v.w * nv.w, h23, m23);
                int e = row * PLDb + dq;
                *(uint2*)(pl + AH_OFF + e) = make_uint2(h01, h23);
                *(uint2*)(pl + AM_OFF + e) = make_uint2(m01, m23);
            }
            // B
            {
                float4 v  = (row < rl) ? *(const float4*)(rbase + (size_t)row * BD + c0 + dq) : z4;
                float4 nv = *(const float4*)(g_invR + row * Dn + c0 + dq);
                uint32_t h01, m01, h23, m23;
                split_pair(v.x * nv.x, v.y * nv.y, h01, m01);
                split_pair(v.z * nv.z, v.w * nv.w, h23, m23);
                int e = row * PLDb + dq;
                *(uint2*)(pl + BH_OFF + e) = make_uint2(h01, h23);
                *(uint2*)(pl + BM_OFF + e) = make_uint2(m01, m23);
            }
        }
        __syncthreads();

        if (act0) {
#pragma unroll
            for (int ks = 0; ks < KCg / 16; ks++) {
                const int k0 = ks * 16;
                wmma::fragment<wmma::matrix_a, 16, 16, 16, __nv_bfloat16,
                               wmma::row_major> ah[2], am[2];
                {
                    const int r0 = 32 * warp_m;
                    wmma::load_matrix_sync(ah[0], pl + AH_OFF + r0 * PLDb + k0, PLDb);
                    wmma::load_matrix_sync(am[0], pl + AM_OFF + r0 * PLDb + k0, PLDb);
                    if (act1) {
                        wmma::load_matrix_sync(ah[1], pl + AH_OFF + (r0 + 16) * PLDb + k0, PLDb);
                        wmma::load_matrix_sync(am[1], pl + AM_OFF + (r0 + 16) * PLDb + k0, PLDb);
                    }
                }
#pragma unroll
                for (int n = 0; n < 4; n++) {
                    const int n0 = 64 * warp_n + 16 * n;
                    if (n0 >= rl) continue;                 // B tile fully masked
                    wmma::fragment<wmma::matrix_b, 16, 16, 16, __nv_bfloat16,
                                   wmma::col_major> bh, bm;
                    wmma::load_matrix_sync(bh, pl + BH_OFF + n0 * PLDb + k0, PLDb);
                    wmma::load_matrix_sync(bm, pl + BM_OFF + n0 * PLDb + k0, PLDb);
                    wmma::mma_sync(cf[0][n], ah[0], bh, cf[0][n]);
                    wmma::mma_sync(cf[0][n], am[0], bh, cf[0][n]);
                    wmma::mma_sync(cf[0][n], ah[0], bm, cf[0][n]);
                    if (act1) {
                        wmma::mma_sync(cf[1][n], ah[1], bh, cf[1][n]);
                        wmma::mma_sync(cf[1][n], am[1], bh, cf[1][n]);
                        wmma::mma_sync(cf[1][n], ah[1], bm, cf[1][n]);
                    }
                }
            }
        }
        __syncthreads();
    }

    // -------- epilogue: fragments -> att, then mask in place --------
#pragma unroll
    for (int i = 0; i < 2; i++)
#pragma unroll
        for (int n = 0; n < 4; n++) {
            const int r0 = 32 * warp_m + 16 * i;
            const int n0 = 64 * warp_n + 16 * n;
            wmma::store_matrix_sync(att + r0 * ATTLD + n0, cf[i][n], ATTLD,
                                    wmma::mem_row_major);
        }
    __syncthreads();

#pragma unroll
    for (int j = 0; j < 16; j++) {
        int i4  = tid + 256 * j;          // 4096 float4 = 128 x 128
        int row = i4 >> 5;
        int c4  = (i4 & 31) << 2;
        float4* p = (float4*)(att + row * ATTLD + c4);
        float4 v = *p;
        float lmv = lm[row];
        v.x *= lmv * rm[c4 + 0];
        v.y *= lmv * rm[c4 + 1];
        v.z *= lmv * rm[c4 + 2];
        v.w *= lmv * rm[c4 + 3];
        *p = v;
    }
    __syncthreads();

    // -------- reductions with fp64 near-tie refinement --------
    for (int r8 = 0; r8 < 16; r8++) {
        int row = wid * 16 + r8;
        float best = att[row * ATTLD + lane];
        int   bi   = lane;
#pragma unroll
        for (int m = 1; m < 4; m++) {
            float v = att[row * ATTLD + lane + 32 * m];
            if (v > best) { best = v; bi = lane + 32 * m; }
        }
#pragma unroll
        for (int off = 16; off; off >>= 1) {
            float ov = __shfl_xor_sync(0xffffffffu, best, off);
            int   oi = __shfl_xor_sync(0xffffffffu, bi,   off);
            if (ov > best || (ov == best && oi < bi)) { best = ov; bi = oi; }
        }
        float thr = best - EPS;
        int cnt = 0;
#pragma unroll
        for (int m = 0; m < 4; m++) {
            float v = att[row * ATTLD + m * 32 + lane];
            cnt += __popc(__ballot_sync(0xffffffffu, v >= thr));
        }
        int fi = bi;
        if (cnt >= 2) {
            bool zmode = (best == 0.0f);
            double bbest;
            int    bbi;
            if (zmode) { bbest = 0.0; bbi = bi; }
            else       { bbest = -1e300; bbi = -1; }
#pragma unroll
            for (int m = 0; m < 4; m++) {
                float v = att[row * ATTLD + m * 32 + lane];
                bool near = (v >= thr) && (!zmode || v != 0.0f);
                unsigned bal = __ballot_sync(0xffffffffu, near);
                while (bal) {
                    int ln = __ffs(bal) - 1;
                    bal &= bal - 1;
                    int cand = m * 32 + ln;
                    bool masked = (lm[row] == 0.0f) || (rm[cand] == 0.0f);
                    double val = masked ? 0.0 : dot64(left, right, row, cand, b);
                    if (val > bbest || (val == bbest && cand < bbi)) { bbest = val; bbi = cand; }
                }
            }
            fi = bbi;
        }
        if (lane == 0) {
            out[LS_OFF + (size_t)row * Bn + b] = att[row * ATTLD + fi];
            g_lidx[b * Ln + row] = fi;
        }
    }

    for (int c8 = 0; c8 < 16; c8++) {
        int col = wid * 16 + c8;
        float best = att[lane * ATTLD + col];
        int   bi   = lane;
#pragma unroll
        for (int m = 1; m < 4; m++) {
            float v = att[(lane + 32 * m) * ATTLD + col];
            if (v > best) { best = v; bi = lane + 32 * m; }
        }
#pragma unroll
        for (int off = 16; off; off >>= 1) {
            float ov = __shfl_xor_sync(0xffffffffu, best, off);
            int   oi = __shfl_xor_sync(0xffffffffu, bi,   off);
            if (ov > best || (ov == best && oi < bi)) { best = ov; bi = oi; }
        }
        float thr = best - EPS;
        int cnt = 0;
#pragma unroll
        for (int m = 0; m < 4; m++) {
            float v = att[(m * 32 + lane) * ATTLD + col];
            cnt += __popc(__ballot_sync(0xffffffffu, v >= thr));
        }
        int fi = bi;
        if (cnt >= 2) {
            bool zmode = (best == 0.0f);
            double bbest;
            int    bbi;
            if (zmode) { bbest = 0.0; bbi = bi; }
            else       { bbest = -1e300; bbi = -1; }
#pragma unroll
            for (int m = 0; m < 4; m++) {
                float v = att[(m * 32 + lane) * ATTLD + col];
                bool near = (v >= thr) && (!zmode || v != 0.0f);
                unsigned bal = __ballot_sync(0xffffffffu, near);
                while (bal) {
                    int ln = __ffs(bal) - 1;
                    bal &= bal - 1;
                    int cand = m * 32 + ln;
                    bool masked = (lm[cand] == 0.0f) || (rm[col] == 0.0f);
                    double val = masked ? 0.0 : dot64(left, right, cand, col, b);
                    if (val > bbest || (val == bbest && cand < bbi)) { bbest = val; bbi = cand; }
                }
            }
            fi = bbi;
        }
        if (lane == 0) {
            out[RS_OFF + (size_t)col * Bn + b] = att[fi * ATTLD + col];
            g_ridx[b * Rn + col] = fi;
        }
    }
}

// ---------------------------------------------------------------------------
// Kernel 3: difference gathers, pure streaming at full occupancy.
// R8 structure + streaming cache hints: sequential loads/stores marked
// evict-first (__ldcs/__stcs) so L2 ways stay available for the gathers.
// ---------------------------------------------------------------------------
__global__ __launch_bounds__(256) void diff_kernel(const float* __restrict__ left,
                                                   const int*   __restrict__ llen,
                                                   const float* __restrict__ right,
                                                   const int*   __restrict__ rlen,
                                                   float*       __restrict__ out) {
    const int PER_SIDE = Ln * Bn * ROW4;
    int g = blockIdx.x * blockDim.x + threadIdx.x;
    bool isL = (g < PER_SIDE);
    int i4 = isL ? g : g - PER_SIDE;

    int l   = i4 / (Bn * ROW4);
    int rem = i4 - l * (Bn * ROW4);
    int b   = rem / ROW4;
    int dq  = rem - b * ROW4;

    const float4* l4 = (const float4*)left;
    const float4* r4 = (const float4*)right;

    float4 res = make_float4(0.f, 0.f, 0.f, 0.f);
    if (isL) {
        if (l < llen[b]) {
            int idx = g_lidx[b * Ln + l];
            float4 a = __ldcs(&l4[i4]);
            float4 c = __ldg(&r4[(size_t)idx * BD4 + (size_t)b * ROW4 + dq]);
            res = make_float4(a.x - c.x, a.y - c.y, a.z - c.z, a.w - c.w);
        }
        __stcs(&((float4*)(out + LD_OFF))[i4], res);
    } else {
        if (l < rlen[b]) {
            int idx = g_ridx[b * Rn + l];
            float4 a = __ldcs(&r4[i4]);
            float4 c = __ldg(&l4[(size_t)idx * BD4 + (size_t)b * ROW4 + dq]);
            res = make_float4(a.x - c.x, a.y - c.y, a.z - c.z, a.w - c.w);
        }
        __stcs(&((float4*)(out + RD_OFF))[i4], res);
    }
}

// ---------------------------------------------------------------------------
extern "C" void kernel_launch(void* const* d_in, const int* in_sizes, int n_in,
                              void* d_out, int out_size) {
    (void)in_sizes; (void)n_in; (void)out_size;
    const float* left  = (const float*)d_in[0];
    const int*   llen  = (const int*)d_in[1];
    const float* right = (const float*)d_in[2];
    const int*   rlen  = (const int*)d_in[3];
    float* out = (float*)d_out;

    cudaFuncSetAttribute(main_kernel, cudaFuncAttributeMaxDynamicSharedMemorySize,
                         DSMEM_BYTES);

    norms_kernel<<<(2 * Ln * Dn) / 256, 256>>>(left, right);
    main_kernel<<<Bn, 256, DSMEM_BYTES>>>(left, llen, right, rlen, out);

    const int PER_SIDE = Ln * Bn * ROW4;
    diff_kernel<<<(2 * PER_SIDE) / 256, 256>>>(left, llen, right, rlen, out);
}